// round 16
// baseline (speedup 1.0000x reference)
#include <cuda_runtime.h>
#include <cuda_bf16.h>
#include <cstdint>

#define B_ 4096
#define T_ 24
#define I_ 128
#define H_ 512
#define WD_ 32
#define M_ (B_*T_)

typedef unsigned int u32; typedef unsigned long long u64; typedef __nv_bfloat16 bf16;

// ---------- scratch (device globals; [0]=hi, [1]=lo) ----------
__device__ __align__(16) bf16 g_x[2][M_*I_], g_xw[2][M_*WD_], g_e[2][M_*H_];
__device__ __align__(16) float g_pre_o[M_*H_], g_pre_r[M_*H_], g_pre_z[M_*H_], g_pre_h[M_*H_];
__device__ __align__(16) bf16 g_h[2][B_*H_], g_hob[2][B_*H_], g_ab[2][B_*H_];
__device__ __align__(16) float g_ho[B_*H_], g_z[B_*H_];
__device__ __align__(16) bf16 g_Wrz[2][1024*640], g_Wo[2][512*384], g_Whx[2][512*128];
__device__ __align__(16) bf16 g_Wt[2][512*512], g_Wrzh[2][1024*512], g_Whh[2][512*512], g_We[2][512*WD_];

__device__ __forceinline__ float sigf(float x){ return 1.f/(1.f + __expf(-x)); }
__device__ __forceinline__ float tanhfast(float x){ return 2.f*sigf(2.f*x) - 1.f; }
__device__ __forceinline__ void spst(bf16* hi, bf16* lo, int idx, float v){
    bf16 h = __float2bfloat16(v);
    hi[idx] = h; lo[idx] = __float2bfloat16(v - __bfloat162float(h));
}
__device__ __forceinline__ u32 s2u(const void* p){
    u32 a; asm("{ .reg .u64 t; cvta.to.shared.u64 t, %1; cvt.u32.u64 %0, t; }" : "=r"(a) : "l"(p)); return a;
}
__device__ __forceinline__ void ldsm4(u32* r, u32 addr){
    asm volatile("ldmatrix.sync.aligned.m8n8.x4.shared.b16 {%0,%1,%2,%3}, [%4];"
        : "=r"(r[0]), "=r"(r[1]), "=r"(r[2]), "=r"(r[3]) : "r"(addr));
}
__device__ __forceinline__ void mmab(float* c, const u32* a, const u32* b){
    asm volatile("mma.sync.aligned.m16n8k16.row.col.f32.bf16.bf16.f32 "
        "{%0,%1,%2,%3}, {%4,%5,%6,%7}, {%8,%9}, {%0,%1,%2,%3};"
        : "+f"(c[0]), "+f"(c[1]), "+f"(c[2]), "+f"(c[3])
        : "r"(a[0]), "r"(a[1]), "r"(a[2]), "r"(a[3]), "r"(b[0]), "r"(b[1]));
}
__device__ __forceinline__ void cpa(u32 s, const void* g, int sz){
    asm volatile("cp.async.cg.shared.global [%0], [%1], 16, %2;" :: "r"(s), "l"(g), "r"(sz) : "memory");
}
__device__ __forceinline__ void cpcommit(){ asm volatile("cp.async.commit_group;" ::: "memory"); }
template<int N> __device__ __forceinline__ void cpwait(){ asm volatile("cp.async.wait_group %0;" :: "n"(N) : "memory"); }
__device__ __forceinline__ void barns(int id, int cnt){
    asm volatile("bar.sync %0, %1;" :: "r"(id), "r"(cnt) : "memory");
}

// cluster-scope barrier
__device__ __forceinline__ void csync(){
    __threadfence();
    asm volatile("barrier.cluster.arrive.aligned;" ::: "memory");
    asm volatile("barrier.cluster.wait.aligned;" ::: "memory");
}

// ---------- prep ----------
__global__ void prep_k(const float* __restrict__ x, const float* __restrict__ xw,
    const float* __restrict__ w_rx, const float* __restrict__ w_rh, const float* __restrict__ w_re,
    const float* __restrict__ w_zx, const float* __restrict__ w_zh, const float* __restrict__ w_ze,
    const float* __restrict__ w_hx, const float* __restrict__ w_hh,
    const float* __restrict__ w_d,  const float* __restrict__ w_w,  const float* __restrict__ w_m,
    const float* __restrict__ w_t,  const float* __restrict__ w_e)
{
    int i = blockIdx.x*256 + threadIdx.x;
    if (i < M_*I_)  spst(g_x[0],  g_x[1],  i, x[i]);
    if (i < M_*WD_) spst(g_xw[0], g_xw[1], i, xw[i]);
    if (i < B_*H_){ g_h[0][i] = __float2bfloat16(0.f); g_h[1][i] = __float2bfloat16(0.f); }
    if (i < 1024*640){
        int r = i/640, c = i - r*640; float v;
        if (r < 512) v = (c < 128) ? w_rx[r*128+c] : w_re[r*512 + c - 128];
        else { int rr = r-512; v = (c < 128) ? w_zx[rr*128+c] : w_ze[rr*512 + c - 128]; }
        spst(g_Wrz[0], g_Wrz[1], i, v);
    }
    if (i < 512*384){
        int r = i/384, c = i - r*384; int s = c >> 7;
        const float* p = (s==0) ? w_d : (s==1) ? w_w : w_m;
        spst(g_Wo[0], g_Wo[1], i, p[r*128 + (c & 127)]);
    }
    if (i < 512*128) spst(g_Whx[0], g_Whx[1], i, w_hx[i]);
    if (i < 512*512){ spst(g_Wt[0], g_Wt[1], i, w_t[i]); spst(g_Whh[0], g_Whh[1], i, w_hh[i]); }
    if (i < 1024*512){
        int r = i >> 9, c = i & 511;
        spst(g_Wrzh[0], g_Wrzh[1], i, (r < 512) ? w_rh[r*512+c] : w_zh[(r-512)*512+c]);
    }
    if (i < 512*WD_) spst(g_We[0], g_We[1], i, w_e[i]);
}

// ---------- HMMA GEMM core: 128xBN tile, K32 chunks, bf16x3 split ----------
// Subgroup producer/consumer: A rows for warp-pair p loaded by that pair,
// B rows for quad q loaded by that quad -> named barriers replace __syncthreads.
#define MSZ 8192             // 128 rows * 64 B
#define STG (4*MSZ)          // Ah | Al | Bh | Bl = 32768
#define NSTG 3
#define SMB (NSTG*STG)       // 98304 -> 2 CTAs/SM

__device__ __forceinline__ u32 swz(int r, int c){
    return (u32)(r*64 + ((c ^ ((r>>1)&3))<<4));
}

template<int MODE, int K, int CH, int BN>
__device__ __forceinline__ void gemm_tile(const u32 smu, int bm, int bn, int t,
    const float* __restrict__ bias, const float* __restrict__ bias2, float* __restrict__ out)
{
    const int tid = threadIdx.x, lane = tid & 31, wid = tid >> 5;
    constexpr int NI = (BN == 128) ? 8 : 4;
    constexpr int NQ = NI/2;
    constexpr int HB = BN/2;                  // B rows per quad
    const int m0 = (wid >> 1)*32;
    const int n0 = (wid & 1)*(BN == 128 ? 64 : 32);
    const int pairb = 1 + (wid >> 1);         // named barrier ids
    const int quadb = 5 + (wid & 1);

    const bf16 *BH, *BL;
    if      (MODE==0){ BH=g_We[0];   BL=g_We[1];   }
    else if (MODE==1){ BH=g_Wrz[0];  BL=g_Wrz[1];  }
    else if (MODE==2){ BH=g_Wo[0];   BL=g_Wo[1];   }
    else if (MODE==3){ BH=g_Whx[0];  BL=g_Whx[1];  }
    else if (MODE==4){ BH=g_Wt[0];   BL=g_Wt[1];   }
    else if (MODE==5){ BH=g_Wrzh[0]; BL=g_Wrzh[1]; }
    else             { BH=g_Whh[0];  BL=g_Whh[1];  }

    float acc[2][NI][4];
#pragma unroll
    for (int a=0;a<2;a++)
#pragma unroll
        for (int b=0;b<NI;b++)
#pragma unroll
            for (int c=0;c<4;c++) acc[a][b][c] = 0.f;

    auto issue = [&](int ch){
        const int k0 = ch*32;
        const u32 sbase = smu + (u32)((ch % NSTG)*STG);
        // A: warp-pair p loads its own 32 rows [p*32, p*32+32)
        {
            int tid2 = (wid & 1)*32 + lane;          // 0..63 within pair
#pragma unroll
            for (int s = 0; s < 2; s++){
                int slot = tid2*2 + s;               // 0..127
                int r = (wid >> 1)*32 + (slot >> 2);
                int c = slot & 3;
                int kk = k0 + c*8;
                int gm = bm + r;
                u32 so = sbase + swz(r, c);
                const bf16 *pH = g_x[0], *pL = g_x[1];
                int sz = 16;
                if (MODE == 0){
                    pH = g_xw[0]+gm*WD_+kk; pL = g_xw[1]+gm*WD_+kk;
                } else if (MODE == 1){
                    if (kk < I_){ pH = g_x[0]+gm*I_+kk; pL = g_x[1]+gm*I_+kk; }
                    else        { pH = g_e[0]+gm*H_+kk-I_; pL = g_e[1]+gm*H_+kk-I_; }
                } else if (MODE == 2){
                    int seg = kk >> 7, sh = (seg==0) ? 1 : (seg==1) ? 7 : 30;
                    int b = gm / T_;
                    if (b >= sh){ int s0 = (gm - sh*T_)*I_ + (kk & 127); pH = g_x[0]+s0; pL = g_x[1]+s0; }
                    else sz = 0;
                } else if (MODE == 3){ pH = g_x[0]+gm*I_+kk;  pL = g_x[1]+gm*I_+kk; }
                else if (MODE == 4){ pH = g_h[0]+gm*H_+kk;    pL = g_h[1]+gm*H_+kk; }
                else if (MODE == 5){ pH = g_hob[0]+gm*H_+kk;  pL = g_hob[1]+gm*H_+kk; }
                else               { pH = g_ab[0]+gm*H_+kk;   pL = g_ab[1]+gm*H_+kk; }
                cpa(so, pH, sz); cpa(so + MSZ, pL, sz);
            }
        }
        // B: quad q loads its own HB rows [q*HB, q*HB+HB)
        {
            int tid4 = (wid >> 1)*32 + lane;         // 0..127 within quad
#pragma unroll
            for (int s = 0; s < HB/32; s++){
                int slot = tid4 + s*128;             // 0..HB*4-1
                int r = (wid & 1)*HB + (slot >> 2);
                int c = slot & 3;
                int kk = k0 + c*8;
                int gn = bn + r;
                u32 so = sbase + 2*MSZ + swz(r, c);
                cpa(so, BH + gn*K + kk, 16); cpa(so + MSZ, BL + gn*K + kk, 16);
            }
        }
        cpcommit();
    };

    // per-lane ldmatrix bases
    const int arow = m0 + (lane&7) + ((lane>>3)&1)*8;
    const u32 aoff = (u32)(arow*64);
    const int axr = (arow>>1)&3, ac0 = (lane>>4)&1;
    const int brow = n0 + (lane&7) + ((lane>>4)&1)*8;
    const u32 boff = (u32)(brow*64);
    const int bxr = (brow>>1)&3, bc0 = (lane>>3)&1;

    barns(pairb, 64); barns(quadb, 128);   // protect stage reuse across tiles
    issue(0);
    if (1 < CH) issue(1);

#pragma unroll 1
    for (int ch = 0; ch < CH; ch++){
        if (ch + 1 < CH) cpwait<1>(); else cpwait<0>();
        barns(pairb, 64);                  // A region ready & free
        barns(quadb, 128);                 // B region ready & free
        if (ch + 2 < CH) issue(ch + 2);

        const u32 sbase = smu + (u32)((ch % NSTG)*STG);
#pragma unroll
        for (int ks = 0; ks < 2; ks++){
            const u32 aAd = sbase + aoff + (u32)((((ac0 + 2*ks) ^ axr))<<4);
            const u32 bAd = sbase + 2*MSZ + boff + (u32)((((bc0 + 2*ks) ^ bxr))<<4);
            u32 ah[2][4], al[2][4], bh[NQ][4], bl[NQ][4];
            ldsm4(ah[0], aAd);
            ldsm4(al[0], aAd + MSZ);
            ldsm4(ah[1], aAd + 1024);
            ldsm4(al[1], aAd + MSZ + 1024);
#pragma unroll
            for (int nq = 0; nq < NQ; nq++){
                ldsm4(bh[nq], bAd + nq*1024);
                ldsm4(bl[nq], bAd + MSZ + nq*1024);
            }
#pragma unroll
            for (int ni = 0; ni < NI; ni++){
                const u32* ph = &bh[ni>>1][(ni&1)*2];
                mmab(acc[0][ni], ah[0], ph);
                mmab(acc[1][ni], ah[1], ph);
            }
#pragma unroll
            for (int ni = 0; ni < NI; ni++){
                const u32* pl = &bl[ni>>1][(ni&1)*2];
                mmab(acc[0][ni], ah[0], pl);
                mmab(acc[1][ni], ah[1], pl);
            }
#pragma unroll
            for (int ni = 0; ni < NI; ni++){
                const u32* ph = &bh[ni>>1][(ni&1)*2];
                mmab(acc[0][ni], al[0], ph);
                mmab(acc[1][ni], al[1], ph);
            }
        }
    }

    // ---------- epilogue ----------
#pragma unroll
    for (int mi = 0; mi < 2; mi++){
#pragma unroll
        for (int half = 0; half < 2; half++){
            const int gm = bm + m0 + mi*16 + (lane>>2) + half*8;
#pragma unroll
            for (int ni = 0; ni < NI; ni++){
                const int gn = bn + n0 + ni*8 + (lane&3)*2;
                float v0 = acc[mi][ni][half*2+0];
                float v1 = acc[mi][ni][half*2+1];
                if (MODE == 0){
                    spst(g_e[0], g_e[1], gm*H_+gn,   sigf(v0 + bias[gn]));
                    spst(g_e[0], g_e[1], gm*H_+gn+1, sigf(v1 + bias[gn+1]));
                } else if (MODE == 1){
                    int b = gm/T_, tt = gm - b*T_; int base = (tt*B_ + b)*H_;
                    if (gn < H_){
                        g_pre_r[base+gn]   = v0 + bias[gn];
                        g_pre_r[base+gn+1] = v1 + bias[gn+1];
                    } else {
                        g_pre_z[base+gn-H_]   = v0 + bias2[gn-H_];
                        g_pre_z[base+gn-H_+1] = v1 + bias2[gn-H_+1];
                    }
                } else if (MODE == 2){
                    int b = gm/T_, tt = gm - b*T_; int base = (tt*B_ + b)*H_;
                    g_pre_o[base+gn] = v0; g_pre_o[base+gn+1] = v1;
                } else if (MODE == 3){
                    int b = gm/T_, tt = gm - b*T_; int base = (tt*B_ + b)*H_;
                    g_pre_h[base+gn]   = v0 + bias[gn];
                    g_pre_h[base+gn+1] = v1 + bias[gn+1];
                } else if (MODE == 4){
                    int pb = (t*B_ + gm)*H_ + gn, hb = gm*H_ + gn;
                    float h0 = sigf(g_pre_o[pb]   + v0);
                    float h1 = sigf(g_pre_o[pb+1] + v1);
                    g_ho[hb] = h0; g_ho[hb+1] = h1;
                    spst(g_hob[0], g_hob[1], hb,   h0);
                    spst(g_hob[0], g_hob[1], hb+1, h1);
                } else if (MODE == 5){
                    if (gn < H_){
                        int pb = (t*B_ + gm)*H_ + gn, hb = gm*H_ + gn;
                        float r0 = sigf(g_pre_r[pb]   + v0);
                        float r1 = sigf(g_pre_r[pb+1] + v1);
                        spst(g_ab[0], g_ab[1], hb,   r0 * g_ho[hb]);
                        spst(g_ab[0], g_ab[1], hb+1, r1 * g_ho[hb+1]);
                    } else {
                        int n2 = gn - H_;
                        int pb = (t*B_ + gm)*H_ + n2, hb = gm*H_ + n2;
                        g_z[hb]   = sigf(g_pre_z[pb]   + v0);
                        g_z[hb+1] = sigf(g_pre_z[pb+1] + v1);
                    }
                } else {
                    int pb = (t*B_ + gm)*H_ + gn, hb = gm*H_ + gn;
                    float ht0 = tanhfast(g_pre_h[pb]   + v0);
                    float ht1 = tanhfast(g_pre_h[pb+1] + v1);
                    float z0 = g_z[hb], z1 = g_z[hb+1];
                    float h0 = (1.f - z0)*g_ho[hb]   + z0*ht0;
                    float h1 = (1.f - z1)*g_ho[hb+1] + z1*ht1;
                    spst(g_h[0], g_h[1], hb,   h0);
                    spst(g_h[0], g_h[1], hb+1, h1);
                    out[(gm*T_ + t)*H_ + gn]   = h0;
                    out[(gm*T_ + t)*H_ + gn+1] = h1;
                }
            }
        }
    }
}

// ---------- precompute kernels ----------
template<int MODE, int K, int CH>
__global__ void __launch_bounds__(256, 2)
mm_k(const float* __restrict__ bias, const float* __restrict__ bias2,
     float* __restrict__ out, int t)
{
    extern __shared__ __align__(128) char sm_[];
    gemm_tile<MODE, K, CH, 128>(s2u(sm_), blockIdx.y*128, blockIdx.x*128, t, bias, bias2, out);
}

// ---------- recurrence: 32 clusters of 8 CTAs (256 CTAs, 2/SM) ----------
__global__ void __launch_bounds__(256, 2) __cluster_dims__(8, 1, 1)
rec_k(float* __restrict__ out)
{
    extern __shared__ __align__(128) char sm_[];
    const u32 smu = s2u(sm_);
    const int q = blockIdx.x;          // 0..255; cluster = q>>3, rank = q&7
    const int bm = (q >> 3)*128;
#pragma unroll 1
    for (int t = 0; t < T_; t++){
        gemm_tile<4,512,16, 64>(smu, bm, (q&7)*64,  t, nullptr, nullptr, nullptr);
        csync();
        gemm_tile<5,512,16,128>(smu, bm, (q&7)*128, t, nullptr, nullptr, nullptr);
        csync();
        gemm_tile<6,512,16, 64>(smu, bm, (q&7)*64,  t, nullptr, nullptr, out);
        csync();
    }
}

// ---------- launcher ----------
extern "C" void kernel_launch(void* const* d_in, const int* in_sizes, int n_in,
                              void* d_out, int out_size)
{
    const float* x    = (const float*)d_in[0];
    const float* xw   = (const float*)d_in[1];
    const float* w_rx = (const float*)d_in[2];
    const float* w_rh = (const float*)d_in[3];
    const float* w_re = (const float*)d_in[4];
    const float* b_r  = (const float*)d_in[5];
    const float* w_zx = (const float*)d_in[6];
    const float* w_zh = (const float*)d_in[7];
    const float* w_ze = (const float*)d_in[8];
    const float* b_z  = (const float*)d_in[9];
    const float* w_hx = (const float*)d_in[10];
    const float* w_hh = (const float*)d_in[11];
    const float* b_h  = (const float*)d_in[12];
    const float* w_d  = (const float*)d_in[13];
    const float* w_w  = (const float*)d_in[14];
    const float* w_m  = (const float*)d_in[15];
    const float* w_t  = (const float*)d_in[16];
    const float* w_e  = (const float*)d_in[17];
    const float* b_e  = (const float*)d_in[18];
    float* out = (float*)d_out;

    cudaFuncSetAttribute(mm_k<0, 32, 1>, cudaFuncAttributeMaxDynamicSharedMemorySize, SMB);
    cudaFuncSetAttribute(mm_k<1,640,20>, cudaFuncAttributeMaxDynamicSharedMemorySize, SMB);
    cudaFuncSetAttribute(mm_k<2,384,12>, cudaFuncAttributeMaxDynamicSharedMemorySize, SMB);
    cudaFuncSetAttribute(mm_k<3,128, 4>, cudaFuncAttributeMaxDynamicSharedMemorySize, SMB);
    cudaFuncSetAttribute(rec_k,          cudaFuncAttributeMaxDynamicSharedMemorySize, SMB);

    prep_k<<<(M_*I_ + 255)/256, 256>>>(x, xw, w_rx, w_rh, w_re, w_zx, w_zh, w_ze,
                                       w_hx, w_hh, w_d, w_w, w_m, w_t, w_e);

    mm_k<0, 32, 1><<<dim3(4,768), 256, SMB>>>(b_e, nullptr, nullptr, 0);
    mm_k<1,640,20><<<dim3(8,768), 256, SMB>>>(b_r, b_z,    nullptr, 0);
    mm_k<2,384,12><<<dim3(4,768), 256, SMB>>>(nullptr, nullptr, nullptr, 0);
    mm_k<3,128, 4><<<dim3(4,768), 256, SMB>>>(b_h, nullptr, nullptr, 0);

    rec_k<<<256, 256, SMB>>>(out);
}

// round 17
// speedup vs baseline: 1.1272x; 1.1272x over previous
#include <cuda_runtime.h>
#include <cuda_bf16.h>
#include <cstdint>

#define B_ 4096
#define T_ 24
#define I_ 128
#define H_ 512
#define WD_ 32
#define M_ (B_*T_)

typedef unsigned int u32; typedef unsigned long long u64; typedef __nv_bfloat16 bf16;

// ---------- scratch (device globals; [0]=hi, [1]=lo) ----------
__device__ __align__(16) bf16 g_x[2][M_*I_], g_xw[2][M_*WD_], g_e[2][M_*H_];
__device__ __align__(16) float g_pre_o[M_*H_], g_pre_r[M_*H_], g_pre_z[M_*H_], g_pre_h[M_*H_];
__device__ __align__(16) bf16 g_h[2][B_*H_], g_hob[2][B_*H_], g_ab[2][B_*H_];
__device__ __align__(16) float g_ho[B_*H_], g_z[B_*H_];
__device__ __align__(16) bf16 g_Wrz[2][1024*640], g_Wo[2][512*384], g_Whx[2][512*128];
__device__ __align__(16) bf16 g_Wt[2][512*512], g_Wrzh[2][1024*512], g_Whh[2][512*512], g_We[2][512*WD_];

__device__ __forceinline__ float sigf(float x){ return 1.f/(1.f + __expf(-x)); }
__device__ __forceinline__ float tanhfast(float x){ return 2.f*sigf(2.f*x) - 1.f; }
__device__ __forceinline__ void spst(bf16* hi, bf16* lo, int idx, float v){
    bf16 h = __float2bfloat16(v);
    hi[idx] = h; lo[idx] = __float2bfloat16(v - __bfloat162float(h));
}
__device__ __forceinline__ u32 s2u(const void* p){
    u32 a; asm("{ .reg .u64 t; cvta.to.shared.u64 t, %1; cvt.u32.u64 %0, t; }" : "=r"(a) : "l"(p)); return a;
}
__device__ __forceinline__ void ldsm4(u32* r, u32 addr){
    asm volatile("ldmatrix.sync.aligned.m8n8.x4.shared.b16 {%0,%1,%2,%3}, [%4];"
        : "=r"(r[0]), "=r"(r[1]), "=r"(r[2]), "=r"(r[3]) : "r"(addr));
}
__device__ __forceinline__ void mmab(float* c, const u32* a, const u32* b){
    asm volatile("mma.sync.aligned.m16n8k16.row.col.f32.bf16.bf16.f32 "
        "{%0,%1,%2,%3}, {%4,%5,%6,%7}, {%8,%9}, {%0,%1,%2,%3};"
        : "+f"(c[0]), "+f"(c[1]), "+f"(c[2]), "+f"(c[3])
        : "r"(a[0]), "r"(a[1]), "r"(a[2]), "r"(a[3]), "r"(b[0]), "r"(b[1]));
}
__device__ __forceinline__ void cpa(u32 s, const void* g, int sz){
    asm volatile("cp.async.cg.shared.global [%0], [%1], 16, %2;" :: "r"(s), "l"(g), "r"(sz) : "memory");
}
__device__ __forceinline__ void cpcommit(){ asm volatile("cp.async.commit_group;" ::: "memory"); }
template<int N> __device__ __forceinline__ void cpwait(){ asm volatile("cp.async.wait_group %0;" :: "n"(N) : "memory"); }

// cluster-scope barrier
__device__ __forceinline__ void csync(){
    __threadfence();
    asm volatile("barrier.cluster.arrive.aligned;" ::: "memory");
    asm volatile("barrier.cluster.wait.aligned;" ::: "memory");
}

// ---------- prep ----------
__global__ void prep_k(const float* __restrict__ x, const float* __restrict__ xw,
    const float* __restrict__ w_rx, const float* __restrict__ w_rh, const float* __restrict__ w_re,
    const float* __restrict__ w_zx, const float* __restrict__ w_zh, const float* __restrict__ w_ze,
    const float* __restrict__ w_hx, const float* __restrict__ w_hh,
    const float* __restrict__ w_d,  const float* __restrict__ w_w,  const float* __restrict__ w_m,
    const float* __restrict__ w_t,  const float* __restrict__ w_e)
{
    int i = blockIdx.x*256 + threadIdx.x;
    if (i < M_*I_)  spst(g_x[0],  g_x[1],  i, x[i]);
    if (i < M_*WD_) spst(g_xw[0], g_xw[1], i, xw[i]);
    if (i < B_*H_){ g_h[0][i] = __float2bfloat16(0.f); g_h[1][i] = __float2bfloat16(0.f); }
    if (i < 1024*640){
        int r = i/640, c = i - r*640; float v;
        if (r < 512) v = (c < 128) ? w_rx[r*128+c] : w_re[r*512 + c - 128];
        else { int rr = r-512; v = (c < 128) ? w_zx[rr*128+c] : w_ze[rr*512 + c - 128]; }
        spst(g_Wrz[0], g_Wrz[1], i, v);
    }
    if (i < 512*384){
        int r = i/384, c = i - r*384; int s = c >> 7;
        const float* p = (s==0) ? w_d : (s==1) ? w_w : w_m;
        spst(g_Wo[0], g_Wo[1], i, p[r*128 + (c & 127)]);
    }
    if (i < 512*128) spst(g_Whx[0], g_Whx[1], i, w_hx[i]);
    if (i < 512*512){ spst(g_Wt[0], g_Wt[1], i, w_t[i]); spst(g_Whh[0], g_Whh[1], i, w_hh[i]); }
    if (i < 1024*512){
        int r = i >> 9, c = i & 511;
        spst(g_Wrzh[0], g_Wrzh[1], i, (r < 512) ? w_rh[r*512+c] : w_zh[(r-512)*512+c]);
    }
    if (i < 512*WD_) spst(g_We[0], g_We[1], i, w_e[i]);
}

// ---------- HMMA GEMM core: 128xBN tile, K32 chunks, bf16x3 split ----------
#define MSZ 8192             // 128 rows * 64 B
#define STG (4*MSZ)          // Ah | Al | Bh | Bl = 32768
#define NSTG 3
#define SMB (NSTG*STG)       // 98304 -> 2 CTAs/SM

__device__ __forceinline__ u32 swz(int r, int c){
    return (u32)(r*64 + ((c ^ ((r>>1)&3))<<4));
}

template<int MODE> __device__ __forceinline__ void selB(const bf16*& BH, const bf16*& BL){
    if      (MODE==0){ BH=g_We[0];   BL=g_We[1];   }
    else if (MODE==1){ BH=g_Wrz[0];  BL=g_Wrz[1];  }
    else if (MODE==2){ BH=g_Wo[0];   BL=g_Wo[1];   }
    else if (MODE==3){ BH=g_Whx[0];  BL=g_Whx[1];  }
    else if (MODE==4){ BH=g_Wt[0];   BL=g_Wt[1];   }
    else if (MODE==5){ BH=g_Wrzh[0]; BL=g_Wrzh[1]; }
    else             { BH=g_Whh[0];  BL=g_Whh[1];  }
}

// Prefetch B (static weights) for chunks 0,1 into stages 0,1 — issued BEFORE the
// cluster barrier so loads overlap barrier wait. Entry __syncthreads protects WAR
// against the previous tile's MMA readers.
template<int MODE, int K, int BN>
__device__ __forceinline__ void prefB(const u32 smu, int bn){
    __syncthreads();
    const bf16 *BH, *BL; selB<MODE>(BH, BL);
    const int tid = threadIdx.x;
#pragma unroll
    for (int ch = 0; ch < 2; ch++){
        const u32 sbase = smu + (u32)(ch*STG);
#pragma unroll
        for (int it = 0; it < 2; it++){
            int g = tid + it*256;
            int r = g >> 2, c = g & 3;
            int kk = ch*32 + c*8;
            if (r < BN){
                int gn = bn + r;
                u32 so = sbase + 2*MSZ + swz(r, c);
                cpa(so, BH + gn*K + kk, 16); cpa(so + MSZ, BL + gn*K + kk, 16);
            }
        }
        cpcommit();
    }
}

template<int MODE, int K, int CH, int BN, bool PREB = false>
__device__ __forceinline__ void gemm_tile(const u32 smu, int bm, int bn, int t,
    const float* __restrict__ bias, const float* __restrict__ bias2, float* __restrict__ out)
{
    const int tid = threadIdx.x, lane = tid & 31, wid = tid >> 5;
    constexpr int NI = (BN == 128) ? 8 : 4;    // n-tiles (8-wide) per warp
    constexpr int NQ = NI/2;                   // 16-row B quads per warp
    const int m0 = (wid >> 1)*32;
    const int n0 = (wid & 1)*(BN == 128 ? 64 : 32);

    const bf16 *BH, *BL; selB<MODE>(BH, BL);

    float acc[2][NI][4];
#pragma unroll
    for (int a=0;a<2;a++)
#pragma unroll
        for (int b=0;b<NI;b++)
#pragma unroll
            for (int c=0;c<4;c++) acc[a][b][c] = 0.f;

    auto issue = [&](int ch){
        const int k0 = ch*32;
        const u32 sbase = smu + (u32)((ch % NSTG)*STG);
        const bool doB = !(PREB && ch < 2);
#pragma unroll
        for (int it = 0; it < 2; it++){
            int g = tid + it*256;
            int r = g >> 2, c = g & 3;
            int kk = k0 + c*8;
            int gm = bm + r;
            u32 so = sbase + swz(r, c);
            const bf16 *pH = g_x[0], *pL = g_x[1];
            int sz = 16;
            if (MODE == 0){
                pH = g_xw[0]+gm*WD_+kk; pL = g_xw[1]+gm*WD_+kk;
            } else if (MODE == 1){
                if (kk < I_){ pH = g_x[0]+gm*I_+kk; pL = g_x[1]+gm*I_+kk; }
                else        { pH = g_e[0]+gm*H_+kk-I_; pL = g_e[1]+gm*H_+kk-I_; }
            } else if (MODE == 2){
                int seg = kk >> 7, sh = (seg==0) ? 1 : (seg==1) ? 7 : 30;
                int b = gm / T_;
                if (b >= sh){ int s0 = (gm - sh*T_)*I_ + (kk & 127); pH = g_x[0]+s0; pL = g_x[1]+s0; }
                else sz = 0;
            } else if (MODE == 3){ pH = g_x[0]+gm*I_+kk;  pL = g_x[1]+gm*I_+kk; }
            else if (MODE == 4){ pH = g_h[0]+gm*H_+kk;    pL = g_h[1]+gm*H_+kk; }
            else if (MODE == 5){ pH = g_hob[0]+gm*H_+kk;  pL = g_hob[1]+gm*H_+kk; }
            else               { pH = g_ab[0]+gm*H_+kk;   pL = g_ab[1]+gm*H_+kk; }
            cpa(so, pH, sz); cpa(so + MSZ, pL, sz);

            if (doB && r < BN){
                int gn = bn + r;
                cpa(so + 2*MSZ, BH + gn*K + kk, 16); cpa(so + 3*MSZ, BL + gn*K + kk, 16);
            }
        }
        cpcommit();
    };

    // per-lane ldmatrix bases (row part + swizzle key)
    const int arow = m0 + (lane&7) + ((lane>>3)&1)*8;
    const u32 aoff = (u32)(arow*64);
    const int axr = (arow>>1)&3, ac0 = (lane>>4)&1;
    const int brow = n0 + (lane&7) + ((lane>>4)&1)*8;
    const u32 boff = (u32)(brow*64);
    const int bxr = (brow>>1)&3, bc0 = (lane>>3)&1;

    if (!PREB) __syncthreads();   // protect stage buffers across consecutive tiles
    issue(0);
    if (1 < CH) issue(1);

#pragma unroll 1
    for (int ch = 0; ch < CH; ch++){
        if (ch + 1 < CH) cpwait<1>(); else cpwait<0>();
        __syncthreads();                       // single barrier per chunk
        if (ch + 2 < CH) issue(ch + 2);

        const u32 sbase = smu + (u32)((ch % NSTG)*STG);
#pragma unroll
        for (int ks = 0; ks < 2; ks++){
            const u32 aAd = sbase + aoff + (u32)((((ac0 + 2*ks) ^ axr))<<4);
            const u32 bAd = sbase + 2*MSZ + boff + (u32)((((bc0 + 2*ks) ^ bxr))<<4);
            u32 ah[2][4], al[2][4], bh[NQ][4], bl[NQ][4];
            ldsm4(ah[0], aAd);
            ldsm4(al[0], aAd + MSZ);
            ldsm4(ah[1], aAd + 1024);              // +16 rows (swizzle key invariant)
            ldsm4(al[1], aAd + MSZ + 1024);
#pragma unroll
            for (int nq = 0; nq < NQ; nq++){
                ldsm4(bh[nq], bAd + nq*1024);
                ldsm4(bl[nq], bAd + MSZ + nq*1024);
            }
#pragma unroll
            for (int ni = 0; ni < NI; ni++){
                const u32* ph = &bh[ni>>1][(ni&1)*2];
                mmab(acc[0][ni], ah[0], ph);
                mmab(acc[1][ni], ah[1], ph);
            }
#pragma unroll
            for (int ni = 0; ni < NI; ni++){
                const u32* pl = &bl[ni>>1][(ni&1)*2];
                mmab(acc[0][ni], ah[0], pl);
                mmab(acc[1][ni], ah[1], pl);
            }
#pragma unroll
            for (int ni = 0; ni < NI; ni++){
                const u32* ph = &bh[ni>>1][(ni&1)*2];
                mmab(acc[0][ni], al[0], ph);
                mmab(acc[1][ni], al[1], ph);
            }
        }
    }

    // ---------- epilogue ----------
#pragma unroll
    for (int mi = 0; mi < 2; mi++){
#pragma unroll
        for (int half = 0; half < 2; half++){
            const int gm = bm + m0 + mi*16 + (lane>>2) + half*8;
#pragma unroll
            for (int ni = 0; ni < NI; ni++){
                const int gn = bn + n0 + ni*8 + (lane&3)*2;
                float v0 = acc[mi][ni][half*2+0];
                float v1 = acc[mi][ni][half*2+1];
                if (MODE == 0){
                    spst(g_e[0], g_e[1], gm*H_+gn,   sigf(v0 + bias[gn]));
                    spst(g_e[0], g_e[1], gm*H_+gn+1, sigf(v1 + bias[gn+1]));
                } else if (MODE == 1){
                    int b = gm/T_, tt = gm - b*T_; int base = (tt*B_ + b)*H_;
                    if (gn < H_){
                        g_pre_r[base+gn]   = v0 + bias[gn];
                        g_pre_r[base+gn+1] = v1 + bias[gn+1];
                    } else {
                        g_pre_z[base+gn-H_]   = v0 + bias2[gn-H_];
                        g_pre_z[base+gn-H_+1] = v1 + bias2[gn-H_+1];
                    }
                } else if (MODE == 2){
                    int b = gm/T_, tt = gm - b*T_; int base = (tt*B_ + b)*H_;
                    g_pre_o[base+gn] = v0; g_pre_o[base+gn+1] = v1;
                } else if (MODE == 3){
                    int b = gm/T_, tt = gm - b*T_; int base = (tt*B_ + b)*H_;
                    g_pre_h[base+gn]   = v0 + bias[gn];
                    g_pre_h[base+gn+1] = v1 + bias[gn+1];
                } else if (MODE == 4){
                    int pb = (t*B_ + gm)*H_ + gn, hb = gm*H_ + gn;
                    float h0 = sigf(g_pre_o[pb]   + v0);
                    float h1 = sigf(g_pre_o[pb+1] + v1);
                    g_ho[hb] = h0; g_ho[hb+1] = h1;
                    spst(g_hob[0], g_hob[1], hb,   h0);
                    spst(g_hob[0], g_hob[1], hb+1, h1);
                } else if (MODE == 5){
                    if (gn < H_){
                        int pb = (t*B_ + gm)*H_ + gn, hb = gm*H_ + gn;
                        float r0 = sigf(g_pre_r[pb]   + v0);
                        float r1 = sigf(g_pre_r[pb+1] + v1);
                        spst(g_ab[0], g_ab[1], hb,   r0 * g_ho[hb]);
                        spst(g_ab[0], g_ab[1], hb+1, r1 * g_ho[hb+1]);
                    } else {
                        int n2 = gn - H_;
                        int pb = (t*B_ + gm)*H_ + n2, hb = gm*H_ + n2;
                        g_z[hb]   = sigf(g_pre_z[pb]   + v0);
                        g_z[hb+1] = sigf(g_pre_z[pb+1] + v1);
                    }
                } else {
                    int pb = (t*B_ + gm)*H_ + gn, hb = gm*H_ + gn;
                    float ht0 = tanhfast(g_pre_h[pb]   + v0);
                    float ht1 = tanhfast(g_pre_h[pb+1] + v1);
                    float z0 = g_z[hb], z1 = g_z[hb+1];
                    float h0 = (1.f - z0)*g_ho[hb]   + z0*ht0;
                    float h1 = (1.f - z1)*g_ho[hb+1] + z1*ht1;
                    spst(g_h[0], g_h[1], hb,   h0);
                    spst(g_h[0], g_h[1], hb+1, h1);
                    out[(gm*T_ + t)*H_ + gn]   = h0;
                    out[(gm*T_ + t)*H_ + gn+1] = h1;
                }
            }
        }
    }
}

// ---------- precompute kernels ----------
template<int MODE, int K, int CH>
__global__ void __launch_bounds__(256, 2)
mm_k(const float* __restrict__ bias, const float* __restrict__ bias2,
     float* __restrict__ out, int t)
{
    extern __shared__ __align__(128) char sm_[];
    gemm_tile<MODE, K, CH, 128>(s2u(sm_), blockIdx.y*128, blockIdx.x*128, t, bias, bias2, out);
}

// ---------- recurrence: 32 clusters of 8 CTAs (256 CTAs, 2/SM) ----------
// Static weight tiles (B) of the next phase are prefetched BEFORE each cluster
// barrier so the loads overlap barrier wait; the tile then skips B for chunks 0,1.
__global__ void __launch_bounds__(256, 2) __cluster_dims__(8, 1, 1)
rec_k(float* __restrict__ out)
{
    extern __shared__ __align__(128) char sm_[];
    const u32 smu = s2u(sm_);
    const int q = blockIdx.x;          // 0..255; cluster = q>>3, rank = q&7
    const int bm = (q >> 3)*128;
    const int n64  = (q & 7)*64;
    const int n128 = (q & 7)*128;

    prefB<4,512,64>(smu, n64);                 // Wt for first R1
#pragma unroll 1
    for (int t = 0; t < T_; t++){
        gemm_tile<4,512,16, 64,true>(smu, bm, n64,  t, nullptr, nullptr, nullptr);
        prefB<5,512,128>(smu, n128);           // Wrzh for R2, in flight during csync
        csync();
        gemm_tile<5,512,16,128,true>(smu, bm, n128, t, nullptr, nullptr, nullptr);
        prefB<6,512,64>(smu, n64);             // Whh for R3
        csync();
        gemm_tile<6,512,16, 64,true>(smu, bm, n64,  t, nullptr, nullptr, out);
        prefB<4,512,64>(smu, n64);             // Wt for next step's R1
        csync();
    }
}

// ---------- launcher ----------
extern "C" void kernel_launch(void* const* d_in, const int* in_sizes, int n_in,
                              void* d_out, int out_size)
{
    const float* x    = (const float*)d_in[0];
    const float* xw   = (const float*)d_in[1];
    const float* w_rx = (const float*)d_in[2];
    const float* w_rh = (const float*)d_in[3];
    const float* w_re = (const float*)d_in[4];
    const float* b_r  = (const float*)d_in[5];
    const float* w_zx = (const float*)d_in[6];
    const float* w_zh = (const float*)d_in[7];
    const float* w_ze = (const float*)d_in[8];
    const float* b_z  = (const float*)d_in[9];
    const float* w_hx = (const float*)d_in[10];
    const float* w_hh = (const float*)d_in[11];
    const float* b_h  = (const float*)d_in[12];
    const float* w_d  = (const float*)d_in[13];
    const float* w_w  = (const float*)d_in[14];
    const float* w_m  = (const float*)d_in[15];
    const float* w_t  = (const float*)d_in[16];
    const float* w_e  = (const float*)d_in[17];
    const float* b_e  = (const float*)d_in[18];
    float* out = (float*)d_out;

    cudaFuncSetAttribute(mm_k<0, 32, 1>, cudaFuncAttributeMaxDynamicSharedMemorySize, SMB);
    cudaFuncSetAttribute(mm_k<1,640,20>, cudaFuncAttributeMaxDynamicSharedMemorySize, SMB);
    cudaFuncSetAttribute(mm_k<2,384,12>, cudaFuncAttributeMaxDynamicSharedMemorySize, SMB);
    cudaFuncSetAttribute(mm_k<3,128, 4>, cudaFuncAttributeMaxDynamicSharedMemorySize, SMB);
    cudaFuncSetAttribute(rec_k,          cudaFuncAttributeMaxDynamicSharedMemorySize, SMB);

    prep_k<<<(M_*I_ + 255)/256, 256>>>(x, xw, w_rx, w_rh, w_re, w_zx, w_zh, w_ze,
                                       w_hx, w_hh, w_d, w_w, w_m, w_t, w_e);

    mm_k<0, 32, 1><<<dim3(4,768), 256, SMB>>>(b_e, nullptr, nullptr, 0);
    mm_k<1,640,20><<<dim3(8,768), 256, SMB>>>(b_r, b_z,    nullptr, 0);
    mm_k<2,384,12><<<dim3(4,768), 256, SMB>>>(nullptr, nullptr, nullptr, 0);
    mm_k<3,128, 4><<<dim3(4,768), 256, SMB>>>(b_h, nullptr, nullptr, 0);

    rec_k<<<256, 256, SMB>>>(out);
}